// round 17
// baseline (speedup 1.0000x reference)
#include <cuda_runtime.h>
#include <cuda_fp16.h>
#include <cstdint>

#define Nn 100000
#define Mm 800000
#define CAP 48

// ---------------- device scratch (no allocations allowed) ----------------
__device__ __half    g_h2h[(size_t)Nn * 64];    // h2 rows fp16 (identity word order)
__device__ __half    g_xh[(size_t)Nn * 64];     // x rows fp16 (identity word order)
__device__ uint32_t  g_aggEh[(size_t)Nn * 32];  // fp16 aggE rows; words 24..31 pad
__device__ int       g_cur[Nn];                 // packed: tot(10)|c1(10)|c2(10)
__device__ int       g_slots[(size_t)Nn * CAP]; // src node per bucket slot
__device__ int       g_ovf_cnt;
__device__ int2      g_ovf[8192];               // overflow: (src, dst)
__device__ uint4     g_Wf1[1536];               // h1 B fragments (W1|W5|b5)
__device__ uint4     g_Wf2[1024];               // h2 B fragments (W2)

__device__ __forceinline__ void red_add_h8(uint32_t* p, uint32_t a, uint32_t b,
                                           uint32_t c, uint32_t d) {
    asm volatile("red.global.add.noftz.v4.f16x2 [%0], {%1,%2,%3,%4};"
                 :: "l"(p), "r"(a), "r"(b), "r"(c), "r"(d) : "memory");
}

__device__ __forceinline__ void mma_f16(float c[4], uint32_t a0, uint32_t a1,
                                        uint32_t a2, uint32_t a3,
                                        uint32_t b0, uint32_t b1) {
    asm volatile(
        "mma.sync.aligned.m16n8k16.row.col.f32.f16.f16.f32 "
        "{%0,%1,%2,%3},{%4,%5,%6,%7},{%8,%9},{%0,%1,%2,%3};"
        : "+f"(c[0]), "+f"(c[1]), "+f"(c[2]), "+f"(c[3])
        : "r"(a0), "r"(a1), "r"(a2), "r"(a3), "r"(b0), "r"(b1));
}

__device__ __forceinline__ uint32_t pack_h2(float a, float b) {
    __half2 h = __floats2half2_rn(a, b);
    return *(uint32_t*)&h;
}

__device__ __forceinline__ uint32_t hadd2u(uint32_t a, uint32_t b) {
    __half2 r = __hadd2(*(__half2*)&a, *(__half2*)&b);
    return *(uint32_t*)&r;
}

// ---------------- kernels ----------------

// init = prep (B fragments) + conv (x -> fp16) + zero (aggE, cursors)
__global__ void init_kernel(const float* __restrict__ x,
                            const float* __restrict__ W1,
                            const float* __restrict__ W2,
                            const float* __restrict__ W5,
                            const float* __restrict__ b5) {
    int gid = blockIdx.x * blockDim.x + threadIdx.x;
    int stride = gridDim.x * blockDim.x;

    for (int idx = gid; idx < 1536; idx += stride) {
        int ln = idx & 31;
        int ntp = (idx >> 5) & 3;
        int kb = idx >> 7;                    // 0..11
        int tqf = ln & 3, gf = ln >> 2;
        int col0 = (2 * ntp) * 8 + gf;
        int col1 = col0 + 8;
        auto val = [&](int h, int elem, int outc) -> float {
            if (kb < 8) {
                int ty = kb >> 2, p = kb & 3;
                int wd = 16 * (p >> 1) + 4 * tqf + 2 * (p & 1) + h;
                int hh = 2 * wd + elem;
                return W1[(size_t)ty * 4096 + hh * 64 + outc];
            } else {
                int p = kb - 8;
                int wd = 16 * (p >> 1) + 4 * tqf + 2 * (p & 1) + h;
                if (wd < 24) {
                    int t = wd >> 3, colf = 2 * (wd & 7) + elem;
                    return W5[(size_t)(t * 16 + colf) * 64 + outc];
                }
                if (wd == 24) return b5[elem * 64 + outc];
                if (wd == 25) return (elem == 0) ? b5[128 + outc] : 0.f;
                return 0.f;
            }
        };
        uint4 wv;
        wv.x = pack_h2(val(0, 0, col0), val(0, 1, col0));
        wv.y = pack_h2(val(1, 0, col0), val(1, 1, col0));
        wv.z = pack_h2(val(0, 0, col1), val(0, 1, col1));
        wv.w = pack_h2(val(1, 0, col1), val(1, 1, col1));
        g_Wf1[idx] = wv;
    }
    for (int idx = gid; idx < 1024; idx += stride) {
        int ln = idx & 31;
        int ntp = (idx >> 5) & 3;
        int kb = idx >> 7;                    // 0..7
        int tqf = ln & 3, gf = ln >> 2;
        int col0 = (2 * ntp) * 8 + gf;
        int col1 = col0 + 8;
        auto val2 = [&](int h, int elem, int outc) -> float {
            int ty = kb >> 2, p = kb & 3;
            int wd = 16 * (p >> 1) + 4 * tqf + 2 * (p & 1) + h;
            int hh = 2 * wd + elem;
            return W2[(size_t)ty * 4096 + hh * 64 + outc];
        };
        uint4 wv;
        wv.x = pack_h2(val2(0, 0, col0), val2(0, 1, col0));
        wv.y = pack_h2(val2(1, 0, col0), val2(1, 1, col0));
        wv.z = pack_h2(val2(0, 0, col1), val2(0, 1, col1));
        wv.w = pack_h2(val2(1, 0, col1), val2(1, 1, col1));
        g_Wf2[idx] = wv;
    }
    const float4* x4 = (const float4*)x;
    uint2* xo = (uint2*)g_xh;
    for (int i = gid; i < Nn * 16; i += stride) {
        float4 f = x4[i];
        xo[i] = make_uint2(pack_h2(f.x, f.y), pack_h2(f.z, f.w));
    }
    uint4 z = make_uint4(0u, 0u, 0u, 0u);
    uint4* a4 = (uint4*)g_aggEh;
    for (int i = gid; i < Nn * 8; i += stride) a4[i] = z;
    for (int i = gid; i < Nn; i += stride) g_cur[i] = 0;
    if (gid == 0) g_ovf_cnt = 0;
}

// 1 thread/edge: load full ef row, 2x fp16x8 red + packed cursor + bucket fill
__global__ void edge_scatter_kernel(const float* __restrict__ ef,
                                    const int* __restrict__ esrc,
                                    const int* __restrict__ edst,
                                    const int* __restrict__ etype) {
    int e = blockIdx.x * blockDim.x + threadIdx.x;
    if (e >= Mm) return;
    int dst = edst[e];
    int t   = etype[e];
    const float4* ef4 = (const float4*)ef;
    float4 v0 = ef4[e * 4 + 0];
    float4 v1 = ef4[e * 4 + 1];
    float4 v2 = ef4[e * 4 + 2];
    float4 v3 = ef4[e * 4 + 3];
    uint32_t* base = g_aggEh + (size_t)dst * 32 + t * 8;
    red_add_h8(base,     pack_h2(v0.x, v0.y), pack_h2(v0.z, v0.w),
                         pack_h2(v1.x, v1.y), pack_h2(v1.z, v1.w));
    red_add_h8(base + 4, pack_h2(v2.x, v2.y), pack_h2(v2.z, v2.w),
                         pack_h2(v3.x, v3.y), pack_h2(v3.z, v3.w));
    int inc = 1 + ((t == 1) ? (1 << 10) : 0) + ((t == 2) ? (1 << 20) : 0);
    int old = atomicAdd(&g_cur[dst], inc);
    int p = old & 1023;
    int src = esrc[e];
    if (p < CAP) {
        g_slots[(size_t)dst * CAP + p] = src;
    } else {
        int o = atomicAdd(&g_ovf_cnt, 1);
        if (o < 8192) g_ovf[o] = make_int2(src, dst);
    }
}

// Fused GEMM: one pass over nodes. Phase A (8 kb, W2) -> h2h; Phase B
// (12 kb, W1|W5|b5) -> out (FULL write). x fragments shared.
__global__ __launch_bounds__(256, 2)
void fused_gemm_kernel(const int* __restrict__ ntype,
                       const float* __restrict__ b1,
                       const float* __restrict__ b2,
                       float* __restrict__ out) {
    extern __shared__ uint32_t smu[];
    uint4* Wf2 = (uint4*)smu;                 // 1024 uint4 = 16 KB
    uint4* Wf1 = Wf2 + 1024;                  // 1536 uint4 = 24 KB
    float* bc2 = (float*)(Wf1 + 1536);        // [128]
    float* bc1 = bc2 + 128;                   // [128]

    const int tid = threadIdx.x;
    const int w = tid >> 5, lane = tid & 31;
    const int g = lane >> 2, tq = lane & 3;

    for (int idx = tid; idx < 1024; idx += 256) Wf2[idx] = g_Wf2[idx];
    for (int idx = tid; idx < 1536; idx += 256) Wf1[idx] = g_Wf1[idx];
    if (tid < 128) { bc2[tid] = b2[tid]; bc1[tid] = b1[tid]; }
    __syncthreads();

    const int G = Nn >> 4;
    const int nwarps = gridDim.x << 3;
    __half2* h2p = (__half2*)g_h2h;
    float2* outp = (float2*)out;
    const uint4* xh4 = (const uint4*)g_xh;
    const uint4* ag4 = (const uint4*)g_aggEh;

    for (int grp = blockIdx.x * 8 + w; grp < G; grp += nwarps) {
        int base = grp << 4;
        uint4 xu[2][2], tu[2][2];
        uint32_t msk[2];
        int tt[2];
        #pragma unroll
        for (int j = 0; j < 2; j++) {
            int node = base + g + 8 * j;
            tt[j] = __ldg(&ntype[node]);
            msk[j] = (tt[j] == 0) ? 0xFFFFFFFFu : 0u;
            xu[j][0] = __ldg(&xh4[(size_t)node * 8 + tq]);
            xu[j][1] = __ldg(&xh4[(size_t)node * 8 + tq + 4]);
            tu[j][0] = __ldg(&ag4[(size_t)node * 8 + tq]);
            tu[j][1] = __ldg(&ag4[(size_t)node * 8 + tq + 4]);
            int cv = __ldg(&g_cur[node]);
            if (tq == 2) {
                int tot = cv & 1023, c1i = (cv >> 10) & 1023, c2i = cv >> 20;
                tu[j][1].x = pack_h2((float)(tot - c1i - c2i), (float)c1i);
                tu[j][1].y = pack_h2((float)c2i, 0.f);
            }
        }

        auto slot = [&](uint4 uq[2], int p, int h) -> uint32_t {
            uint4 uu = uq[p >> 1];
            return (p & 1) ? (h ? uu.w : uu.z) : (h ? uu.y : uu.x);
        };

        float acc[8][4];

        // ---- phase A: h2 = W2-GEMM -> h2h ----
        #pragma unroll
        for (int nt = 0; nt < 8; nt++)
            #pragma unroll
            for (int jj = 0; jj < 4; jj++) acc[nt][jj] = 0.f;

        #pragma unroll
        for (int kb = 0; kb < 8; kb++) {
            int p = kb & 3;
            uint32_t s0 = (kb < 4) ? msk[0] : ~msk[0];
            uint32_t s1 = (kb < 4) ? msk[1] : ~msk[1];
            uint32_t a0 = slot(xu[0], p, 0) & s0;
            uint32_t a2 = slot(xu[0], p, 1) & s0;
            uint32_t a1 = slot(xu[1], p, 0) & s1;
            uint32_t a3 = slot(xu[1], p, 1) & s1;
            #pragma unroll
            for (int ntp = 0; ntp < 4; ntp++) {
                uint4 bw = Wf2[(kb * 4 + ntp) * 32 + lane];
                mma_f16(acc[2 * ntp], a0, a1, a2, a3, bw.x, bw.y);
                mma_f16(acc[2 * ntp + 1], a0, a1, a2, a3, bw.z, bw.w);
            }
        }
        #pragma unroll
        for (int j = 0; j < 2; j++) {
            int node = base + g + 8 * j;
            int t = tt[j];
            #pragma unroll
            for (int nt = 0; nt < 8; nt++) {
                int col0 = nt * 8 + 2 * tq;
                float v0 = acc[nt][2 * j + 0] + bc2[t * 64 + col0];
                float v1 = acc[nt][2 * j + 1] + bc2[t * 64 + col0 + 1];
                h2p[(size_t)node * 32 + nt * 4 + tq] = __floats2half2_rn(v0, v1);
            }
        }

        // ---- phase B: h1 = (W1|W5|b5)-GEMM -> out ----
        #pragma unroll
        for (int nt = 0; nt < 8; nt++)
            #pragma unroll
            for (int jj = 0; jj < 4; jj++) acc[nt][jj] = 0.f;

        #pragma unroll
        for (int kb = 0; kb < 12; kb++) {
            uint32_t a0, a1, a2, a3;
            if (kb < 8) {
                int p = kb & 3;
                uint32_t s0 = (kb < 4) ? msk[0] : ~msk[0];
                uint32_t s1 = (kb < 4) ? msk[1] : ~msk[1];
                a0 = slot(xu[0], p, 0) & s0;
                a2 = slot(xu[0], p, 1) & s0;
                a1 = slot(xu[1], p, 0) & s1;
                a3 = slot(xu[1], p, 1) & s1;
            } else {
                int p = kb - 8;
                a0 = slot(tu[0], p, 0); a2 = slot(tu[0], p, 1);
                a1 = slot(tu[1], p, 0); a3 = slot(tu[1], p, 1);
            }
            #pragma unroll
            for (int ntp = 0; ntp < 4; ntp++) {
                uint4 bw = Wf1[(kb * 4 + ntp) * 32 + lane];
                mma_f16(acc[2 * ntp], a0, a1, a2, a3, bw.x, bw.y);
                mma_f16(acc[2 * ntp + 1], a0, a1, a2, a3, bw.z, bw.w);
            }
        }
        #pragma unroll
        for (int j = 0; j < 2; j++) {
            int node = base + g + 8 * j;
            int t = tt[j];
            #pragma unroll
            for (int nt = 0; nt < 8; nt++) {
                int col0 = nt * 8 + 2 * tq;
                float v0 = acc[nt][2 * j + 0] + bc1[t * 64 + col0];
                float v1 = acc[nt][2 * j + 1] + bc1[t * 64 + col0 + 1];
                outp[(size_t)node * 32 + nt * 4 + tq] = make_float2(v0, v1);
            }
        }
    }
}

// Bucket gather: out[dst] += sum h2h[src]; 8 lanes/node; pairwise HADD2
// pre-reduction (one extra fp16 rounding per edge pair) into fp32 acc.
__global__ __launch_bounds__(256)
void gatherH_kernel(float* __restrict__ out) {
    int tid = threadIdx.x;
    int node = blockIdx.x * 32 + (tid >> 3);
    int q = tid & 7;
    if (node >= Nn) return;
    int deg_raw = g_cur[node] & 1023;
    int deg = (deg_raw > CAP) ? CAP : deg_raw;
    if (deg == 0) return;

    const uint4* H = (const uint4*)g_h2h;
    const int* sl = &g_slots[(size_t)node * CAP];
    const uint4* sl4 = (const uint4*)sl;
    float acc[8];
    #pragma unroll
    for (int u = 0; u < 8; u++) acc[u] = 0.f;

    auto add8 = [&](uint4 hv) {
        float2 f0 = __half22float2(*(__half2*)&hv.x);
        float2 f1 = __half22float2(*(__half2*)&hv.y);
        float2 f2 = __half22float2(*(__half2*)&hv.z);
        float2 f3 = __half22float2(*(__half2*)&hv.w);
        acc[0] += f0.x; acc[1] += f0.y; acc[2] += f1.x; acc[3] += f1.y;
        acc[4] += f2.x; acc[5] += f2.y; acc[6] += f3.x; acc[7] += f3.y;
    };
    auto addpair = [&](uint4 a, uint4 b) {   // fp16 pair-sum, then fp32 add
        uint4 s;
        s.x = hadd2u(a.x, b.x); s.y = hadd2u(a.y, b.y);
        s.z = hadd2u(a.z, b.z); s.w = hadd2u(a.w, b.w);
        add8(s);
    };

    int i = 0;
    for (; i + 8 <= deg; i += 8) {
        uint4 sa = __ldg(&sl4[i >> 2]);
        uint4 sb = __ldg(&sl4[(i >> 2) + 1]);
        uint4 v0 = __ldg(&H[(size_t)sa.x * 8 + q]);
        uint4 v1 = __ldg(&H[(size_t)sa.y * 8 + q]);
        uint4 v2 = __ldg(&H[(size_t)sa.z * 8 + q]);
        uint4 v3 = __ldg(&H[(size_t)sa.w * 8 + q]);
        uint4 v4 = __ldg(&H[(size_t)sb.x * 8 + q]);
        uint4 v5 = __ldg(&H[(size_t)sb.y * 8 + q]);
        uint4 v6 = __ldg(&H[(size_t)sb.z * 8 + q]);
        uint4 v7 = __ldg(&H[(size_t)sb.w * 8 + q]);
        addpair(v0, v1); addpair(v2, v3);
        addpair(v4, v5); addpair(v6, v7);
    }
    for (; i + 4 <= deg; i += 4) {
        uint4 sa = __ldg(&sl4[i >> 2]);
        uint4 v0 = __ldg(&H[(size_t)sa.x * 8 + q]);
        uint4 v1 = __ldg(&H[(size_t)sa.y * 8 + q]);
        uint4 v2 = __ldg(&H[(size_t)sa.z * 8 + q]);
        uint4 v3 = __ldg(&H[(size_t)sa.w * 8 + q]);
        addpair(v0, v1); addpair(v2, v3);
    }
    for (; i < deg; i++) add8(__ldg(&H[(size_t)__ldg(&sl[i]) * 8 + q]));

    if (deg_raw > CAP) {
        int n = g_ovf_cnt;
        if (n > 8192) n = 8192;
        for (int oi = 0; oi < n; oi++) {
            int2 sd = g_ovf[oi];
            if (sd.y == node) add8(__ldg(&H[(size_t)sd.x * 8 + q]));
        }
    }

    float4* o4 = (float4*)out;
    float4 oa = o4[(size_t)node * 16 + 2 * q];
    float4 ob = o4[(size_t)node * 16 + 2 * q + 1];
    oa.x += acc[0]; oa.y += acc[1]; oa.z += acc[2]; oa.w += acc[3];
    ob.x += acc[4]; ob.y += acc[5]; ob.z += acc[6]; ob.w += acc[7];
    o4[(size_t)node * 16 + 2 * q] = oa;
    o4[(size_t)node * 16 + 2 * q + 1] = ob;
}

// ---------------- launch ----------------
extern "C" void kernel_launch(void* const* d_in, const int* in_sizes, int n_in,
                              void* d_out, int out_size) {
    const float *x = nullptr, *ef = nullptr;
    const float *W[4] = {nullptr, nullptr, nullptr, nullptr};
    const float *B[4] = {nullptr, nullptr, nullptr, nullptr};
    const float *W5 = nullptr, *b5 = nullptr;
    const int *ntype = nullptr, *esrc = nullptr, *edst = nullptr, *etype = nullptr;
    int wI = 0, bI = 0, mI = 0;
    for (int i = 0; i < n_in; i++) {
        long s = in_sizes[i];
        const void* p = d_in[i];
        if (s == (long)Nn * 64)       x = (const float*)p;
        else if (s == (long)Mm * 16)  ef = (const float*)p;
        else if (s == Nn)             ntype = (const int*)p;
        else if (s == Mm) {
            if (mI == 0) esrc = (const int*)p;
            else if (mI == 1) edst = (const int*)p;
            else etype = (const int*)p;
            mI++;
        }
        else if (s == 2 * 64 * 64) { if (wI < 4) W[wI++] = (const float*)p; }
        else if (s == 2 * 64)      { if (bI < 4) B[bI++] = (const float*)p; }
        else if (s == 3 * 16 * 64) W5 = (const float*)p;
        else if (s == 3 * 64)      b5 = (const float*)p;
    }
    float* out = (float*)d_out;

    const int gemm_smem = 2560 * 16 + 256 * 4;   // 41984
    cudaFuncSetAttribute(fused_gemm_kernel,
                         cudaFuncAttributeMaxDynamicSharedMemorySize, 48 * 1024);

    init_kernel<<<2048, 256>>>(x, W[0], W[1], W5, b5);
    edge_scatter_kernel<<<(Mm + 255) / 256, 256>>>(ef, esrc, edst, etype);
    fused_gemm_kernel<<<296, 256, gemm_smem>>>(ntype, B[0], B[1], out);
    gatherH_kernel<<<(Nn + 31) / 32, 256>>>(out);
}